// round 12
// baseline (speedup 1.0000x reference)
#include <cuda_runtime.h>
#include <cuda_bf16.h>
#include <math.h>

#define Bn 32
#define Tn 384
#define Dn 768
#define D3 2304
#define NB 96
#define GRP_NB 48
#define THRESH 0.95f

__device__ float g_xp[(size_t)Bn * Tn * D3];
__device__ float g_states[(size_t)Bn * Tn * Dn];
__device__ float g_probs[Bn * Tn];
__device__ float g_weights[Bn * Tn];
__device__ int   g_segend[Bn * Tn];
__device__ int   g_nsegs[Bn];
__device__ volatile int g_flag[NB];
__device__ int   g_done;

// h exchange in m16n8k8 A-frag layout, per group+parity: [grp][par][96 ktile][128]
__device__ float g_hfrag[2][2][96 * 128];
// w_hh fp32 fragment-permuted per column-slice: [cidx 48][ks 8][q 12][nt 6][lane 32][2]
#define WFG (8 * 12 * 6 * 32 * 2)
__device__ float g_wfrag[(size_t)GRP_NB * WFG];

// xp GEMM operands pre-permuted into bf16 mma-fragment order (hi/lo split):
// A: [m-tile 768][kt 48][lane 32][8 words: a0h..a3h, a0l..a3l]
// B: [n-tile 288][kt 48][lane 32][4 words: b0h, b1h, b0l, b1l]
__device__ unsigned g_fA[(size_t)768 * 48 * 32 * 8];
__device__ unsigned g_fB[(size_t)288 * 48 * 32 * 4];

__device__ __forceinline__ void bsplit(float2 p, unsigned& hi, unsigned& lo) {
    __nv_bfloat16 hx = __float2bfloat16(p.x);
    __nv_bfloat16 hy = __float2bfloat16(p.y);
    __nv_bfloat162 h; h.x = hx; h.y = hy;
    float lx = p.x - __bfloat162float(hx);
    float ly = p.y - __bfloat162float(hy);
    __nv_bfloat162 l = __floats2bfloat162_rn(lx, ly);
    hi = *(unsigned*)&h; lo = *(unsigned*)&l;
}

// ============ prep A: gather emb[sent] -> frag-ordered hi/lo planes
__global__ __launch_bounds__(256) void k_prep_a(const int* __restrict__ sent,
                                                const float* __restrict__ emb) {
    int idx = blockIdx.x * 256 + threadIdx.x;   // over 768*48*32
    int lane = idx & 31;
    int kt = (idx >> 5) % 48;
    int tm = idx / (48 * 32);
    int k0 = kt * 16 + (lane & 3) * 2;
    int m0 = tm * 16 + (lane >> 2);
    const float* x0 = emb + (size_t)sent[m0] * Dn;
    const float* x1 = emb + (size_t)sent[m0 + 8] * Dn;
    float2 p00 = *(const float2*)(x0 + k0);
    float2 p10 = *(const float2*)(x1 + k0);
    float2 p01 = *(const float2*)(x0 + k0 + 8);
    float2 p11 = *(const float2*)(x1 + k0 + 8);
    unsigned* dst = g_fA + (size_t)idx * 8;
    unsigned h, l;
    bsplit(p00, h, l); dst[0] = h; dst[4] = l;
    bsplit(p10, h, l); dst[1] = h; dst[5] = l;
    bsplit(p01, h, l); dst[2] = h; dst[6] = l;
    bsplit(p11, h, l); dst[3] = h; dst[7] = l;
}

// ============ prep B: w_ih -> frag-ordered hi/lo planes
__global__ __launch_bounds__(256) void k_prep_b(const float* __restrict__ w_ih) {
    int idx = blockIdx.x * 256 + threadIdx.x;   // over 288*48*32
    int lane = idx & 31;
    int kt = (idx >> 5) % 48;
    int tn = idx / (48 * 32);
    int n = tn * 8 + (lane >> 2);
    int k0 = kt * 16 + (lane & 3) * 2;
    const float* wr = w_ih + (size_t)n * Dn;
    float2 p0 = *(const float2*)(wr + k0);
    float2 p1 = *(const float2*)(wr + k0 + 8);
    unsigned* dst = g_fB + (size_t)idx * 4;
    unsigned h, l;
    bsplit(p0, h, l); dst[0] = h; dst[2] = l;
    bsplit(p1, h, l); dst[1] = h; dst[3] = l;
}

// ============ prep: w_hh -> fp32 B-fragment layout (per 16-col slice)
__global__ __launch_bounds__(256) void k_prep_w(const float* __restrict__ w_hh) {
    int cidx = blockIdx.x;
    int c0 = cidx * 16;
    for (int it = 0; it < WFG / 256; it++) {
        int idx = it * 256 + threadIdx.x;
        int word = idx & 1;
        int lane = (idx >> 1) & 31;
        int f = idx >> 6;
        int nt = f % 6;
        int q = (f / 6) % 12;
        int ks = f / 72;
        int n = nt * 8 + (lane >> 2);
        int j = n >> 4, col = n & 15;
        int gr = j * Dn + c0 + col;
        int k = ks * 96 + q * 8 + (lane & 3) + 4 * word;
        g_wfrag[(size_t)cidx * WFG + idx] = w_hh[(size_t)gr * Dn + k];
    }
}

// ============ Kernel 1: xp via mma.sync bf16 3-term split, SMEM-free
__device__ __forceinline__ void mma_bf16(float* c, const unsigned* a, const unsigned* b) {
    asm volatile(
        "mma.sync.aligned.m16n8k16.row.col.f32.bf16.bf16.f32 "
        "{%0,%1,%2,%3}, {%4,%5,%6,%7}, {%8,%9}, {%0,%1,%2,%3};"
        : "+f"(c[0]), "+f"(c[1]), "+f"(c[2]), "+f"(c[3])
        : "r"(a[0]), "r"(a[1]), "r"(a[2]), "r"(a[3]), "r"(b[0]), "r"(b[1]));
}

__global__ __launch_bounds__(256, 1) void k_xp_mma(const float* __restrict__ b_ih) {
    const int tid = threadIdx.x;
    const int bm = blockIdx.y * 128;
    const int bn = blockIdx.x * 128;
    const int warp = tid >> 5;
    const int lane = tid & 31;
    const int wm = warp >> 2;       // 0..1
    const int wn = warp & 3;        // 0..3
    const int gid = lane >> 2;
    const int tig = lane & 3;

    // per-lane running fragment indices (uint4 units)
    int aIdx[4], bIdx[4];
#pragma unroll
    for (int i = 0; i < 4; i++) {
        int tA = blockIdx.y * 8 + wm * 4 + i;
        aIdx[i] = (tA * 48 * 32 + lane) * 2;        // step 64 per kt
        int tB = blockIdx.x * 16 + wn * 4 + i;
        bIdx[i] = tB * 48 * 32 + lane;              // step 32 per kt
    }
    const uint4* aptr = (const uint4*)g_fA;
    const uint4* bptr = (const uint4*)g_fB;

    float acc[4][4][4];
#pragma unroll
    for (int i = 0; i < 4; i++)
#pragma unroll
        for (int j = 0; j < 4; j++)
#pragma unroll
            for (int r = 0; r < 4; r++) acc[i][j][r] = 0.f;

    unsigned Ah[2][4][4], Al[2][4][4], Bf[2][4][4];
    // preload kt=0
#pragma unroll
    for (int i = 0; i < 4; i++) {
        *(uint4*)Ah[0][i] = aptr[aIdx[i]];
        *(uint4*)Al[0][i] = aptr[aIdx[i] + 1];
        *(uint4*)Bf[0][i] = bptr[bIdx[i]];
    }

    for (int kt = 0; kt < 48; kt++) {
        const int cb = kt & 1;
        if (kt + 1 < 48) {
            const int nb = cb ^ 1;
#pragma unroll
            for (int i = 0; i < 4; i++) {
                *(uint4*)Ah[nb][i] = aptr[aIdx[i] + (kt + 1) * 64];
                *(uint4*)Al[nb][i] = aptr[aIdx[i] + (kt + 1) * 64 + 1];
                *(uint4*)Bf[nb][i] = bptr[bIdx[i] + (kt + 1) * 32];
            }
        }
#pragma unroll
        for (int i = 0; i < 4; i++)
#pragma unroll
            for (int j = 0; j < 4; j++) {
                mma_bf16(acc[i][j], Ah[cb][i], &Bf[cb][j][0]);
                mma_bf16(acc[i][j], Al[cb][i], &Bf[cb][j][0]);
                mma_bf16(acc[i][j], Ah[cb][i], &Bf[cb][j][2]);
            }
    }

#pragma unroll
    for (int j = 0; j < 4; j++) {
        int ncol = bn + (wn * 4 + j) * 8 + 2 * tig;
        float2 bias = *(const float2*)&b_ih[ncol];
#pragma unroll
        for (int i = 0; i < 4; i++) {
            int m0 = bm + (wm * 4 + i) * 16 + gid;
            float2 v0 = {acc[i][j][0] + bias.x, acc[i][j][1] + bias.y};
            float2 v1 = {acc[i][j][2] + bias.x, acc[i][j][3] + bias.y};
            *(float2*)(g_xp + (size_t)m0 * D3 + ncol) = v0;
            *(float2*)(g_xp + (size_t)(m0 + 8) * D3 + ncol) = v1;
        }
    }
}

// ============ Kernel 2: GRU, 2 groups of 48 blocks; h-frags batch-loaded (MLP 12)
#define SM_PARTG (8 * 48 * 17)
#define SMEM_GRU ((WFG + SM_PARTG) * 4)

__device__ __forceinline__ void mma_tf32(float* c, const float4 a, float b0, float b1) {
    asm volatile(
        "mma.sync.aligned.m16n8k8.row.col.f32.tf32.tf32.f32 "
        "{%0,%1,%2,%3}, {%4,%5,%6,%7}, {%8,%9}, {%0,%1,%2,%3};"
        : "+f"(c[0]), "+f"(c[1]), "+f"(c[2]), "+f"(c[3])
        : "r"(__float_as_uint(a.x)), "r"(__float_as_uint(a.y)),
          "r"(__float_as_uint(a.z)), "r"(__float_as_uint(a.w)),
          "r"(__float_as_uint(b0)), "r"(__float_as_uint(b1)));
}
__device__ __forceinline__ float tf_hi1(float a) {
    return __uint_as_float(__float_as_uint(a) & 0xffffe000u);
}
__device__ __forceinline__ float4 tf_hi(float4 a) {
    return make_float4(tf_hi1(a.x), tf_hi1(a.y), tf_hi1(a.z), tf_hi1(a.w));
}
__device__ __forceinline__ float4 f4sub(float4 a, float4 b) {
    return make_float4(a.x - b.x, a.y - b.y, a.z - b.z, a.w - b.w);
}

__global__ __launch_bounds__(256, 1) void k_gru(const float* __restrict__ b_hh) {
    extern __shared__ float sm[];
    float* wf = sm;                  // [ks][q][nt][lane][2]
    float* part = sm + WFG;          // [ks][48][17]

    const int tid = threadIdx.x;
    const int bid = blockIdx.x;
    const int grp = bid / GRP_NB;
    const int cidx = bid - grp * GRP_NB;
    const int c0 = cidx * 16;
    const int b0 = grp * 16;

    {
        const float4* src = (const float4*)(g_wfrag + (size_t)cidx * WFG);
        float4* dst = (float4*)wf;
        for (int i = tid; i < WFG / 4; i += 256) dst[i] = src[i];
    }

    const int lane = tid & 31;
    const int ks = tid >> 5;

    const int gc = tid >> 4;
    const int gb = tid & 15;
    const float br = b_hh[c0 + gc];
    const float bz = b_hh[Dn + c0 + gc];
    const float bnn = b_hh[2 * Dn + c0 + gc];
    const int c = c0 + gc;
    const int ktile = c >> 3, kin = c & 7;
    const int gw = ktile * 128 + ((gb & 7) * 4 + (kin & 3)) * 4 +
                   ((gb >> 3) + 2 * (kin >> 2));
    float hold = 0.f;

    g_hfrag[grp][0][gw] = 0.f;
    __syncthreads();
    if (tid == 0) { __threadfence(); g_flag[bid] = 1; }
    if (tid < GRP_NB) { while (g_flag[grp * GRP_NB + tid] < 1) {} }
    __threadfence();
    __syncthreads();

    for (int t = 0; t < Tn; t++) {
        const int par = t & 1;

        size_t mrow = (size_t)((b0 + gb) * Tn + t) * D3 + c0 + gc;
        float xr = g_xp[mrow];
        float xz = g_xp[mrow + Dn];
        float xn = g_xp[mrow + 2 * Dn];

        const float* hf = g_hfrag[grp][par];
        const int abase = (ks * 12) * 128 + lane * 4;

        float4 hreg[12];
#pragma unroll
        for (int q = 0; q < 12; q++)
            hreg[q] = __ldcv((const float4*)(hf + abase + q * 128));

        float acc[6][4];
#pragma unroll
        for (int nt = 0; nt < 6; nt++)
#pragma unroll
            for (int r = 0; r < 4; r++) acc[nt][r] = 0.f;

#pragma unroll
        for (int q = 0; q < 12; q++) {
            float4 ahi = tf_hi(hreg[q]);
            float4 alo = f4sub(hreg[q], ahi);
#pragma unroll
            for (int nt = 0; nt < 6; nt++) {
                float2 wv = *(const float2*)&wf[(((ks * 12 + q) * 6) + nt) * 64 + lane * 2];
                float bh0 = tf_hi1(wv.x), bh1 = tf_hi1(wv.y);
                float bl0 = wv.x - bh0, bl1 = wv.y - bh1;
                mma_tf32(acc[nt], ahi, bh0, bh1);
                mma_tf32(acc[nt], alo, bh0, bh1);
                mma_tf32(acc[nt], ahi, bl0, bl1);
            }
        }

#pragma unroll
        for (int nt = 0; nt < 6; nt++)
#pragma unroll
            for (int r = 0; r < 4; r++)
                part[ks * (48 * 17) + (nt * 8 + (lane & 3) * 2 + (r & 1)) * 17 +
                     (lane >> 2) + 8 * (r >> 1)] = acc[nt][r];
        __syncthreads();

        {
            float hr = br, hz = bz, hn = bnn;
#pragma unroll
            for (int s2 = 0; s2 < 8; s2++) {
                const float* pp = part + s2 * (48 * 17);
                hr += pp[gc * 17 + gb];
                hz += pp[(16 + gc) * 17 + gb];
                hn += pp[(32 + gc) * 17 + gb];
            }
            float r = 1.f / (1.f + expf(-(xr + hr)));
            float z = 1.f / (1.f + expf(-(xz + hz)));
            float n = tanhf(xn + r * hn);
            float hnew = (1.f - z) * n + z * hold;
            hold = hnew;
            g_hfrag[grp][par ^ 1][gw] = hnew;
            g_states[(size_t)((b0 + gb) * Tn + t) * Dn + c0 + gc] = hnew;
        }

        __syncthreads();
        if (tid == 0) { __threadfence(); g_flag[bid] = t + 2; }
        if (tid < GRP_NB) { while (g_flag[grp * GRP_NB + tid] < t + 2) {} }
        __threadfence();
        __syncthreads();
    }

    if (tid == 0) {
        int old = atomicAdd(&g_done, 1);
        if (old == NB - 1) {
            for (int i = 0; i < NB; i++) g_flag[i] = 0;
            __threadfence();
            g_done = 0;
        }
    }
}

// ============ Kernel 3: probs
__global__ __launch_bounds__(256) void k_probs(const float* __restrict__ w_act,
                                               const float* __restrict__ b_act,
                                               float* __restrict__ out_probs) {
    int warp = threadIdx.x >> 5, lane = threadIdx.x & 31;
    int m = blockIdx.x * 8 + warp;
    const float4* row = (const float4*)(g_states + (size_t)m * Dn);
    const float4* wv = (const float4*)w_act;
    float acc = 0.f;
    for (int i = lane; i < 192; i += 32) {
        float4 v = row[i], w = wv[i];
        acc += v.x * w.x + v.y * w.y + v.z * w.z + v.w * w.w;
    }
#pragma unroll
    for (int off = 16; off; off >>= 1) acc += __shfl_down_sync(0xffffffffu, acc, off);
    if (lane == 0) {
        float p = 1.f / (1.f + expf(-(acc + b_act[0])));
        g_probs[m] = p;
        out_probs[m] = p;
    }
}

// ============ Kernel 4: ACT halting scan
__global__ void k_halt() {
    extern __shared__ float ps[];
    int tid = threadIdx.x;
    for (int i = tid; i < Bn * Tn; i += 384) {
        int b = i / Tn, t = i - b * Tn;
        ps[b * (Tn + 1) + t] = g_probs[i];
    }
    __syncthreads();
    if (tid < Bn) {
        int b = tid;
        const float* pb = ps + b * (Tn + 1);
        float acc = 0.f;
        int ns = 0;
        for (int t = 0; t < Tn; t++) {
            float p = pb[t];
            float a = acc + p;
            if (a > THRESH) {
                g_weights[b * Tn + t] = p - (a - 1.f);
                g_segend[b * Tn + ns] = t;
                ns++;
                acc = 0.f;
            } else {
                g_weights[b * Tn + t] = p;
                acc = a;
            }
        }
        g_nsegs[b] = ns;
    }
}

// ============ Kernel 5: segment sums -> output embs
__global__ __launch_bounds__(128) void k_out(float* __restrict__ out) {
    int bs = blockIdx.x;
    int b = bs / Tn, s = bs - b * Tn;
    float* o = out + (size_t)bs * Dn;
    int tid = threadIdx.x;
    if (s >= g_nsegs[b]) {
        for (int d = tid; d < Dn; d += 128) o[d] = 0.f;
        return;
    }
    int t1 = g_segend[b * Tn + s];
    int t0 = (s == 0) ? 0 : g_segend[b * Tn + s - 1] + 1;
    for (int d = tid; d < Dn; d += 128) {
        float sum = 0.f;
        for (int t = t0; t <= t1; t++)
            sum += g_states[(size_t)(b * Tn + t) * Dn + d] * g_weights[b * Tn + t];
        o[d] = sum;
    }
}

extern "C" void kernel_launch(void* const* d_in, const int* in_sizes, int n_in,
                              void* d_out, int out_size) {
    const int* sent    = (const int*)d_in[0];
    const float* emb   = (const float*)d_in[1];
    const float* w_ih  = (const float*)d_in[2];
    const float* w_hh  = (const float*)d_in[3];
    const float* b_ih  = (const float*)d_in[4];
    const float* b_hh  = (const float*)d_in[5];
    const float* w_act = (const float*)d_in[6];
    const float* b_act = (const float*)d_in[7];
    float* out = (float*)d_out;

    cudaFuncSetAttribute(k_gru, cudaFuncAttributeMaxDynamicSharedMemorySize, SMEM_GRU);
    cudaFuncSetAttribute(k_halt, cudaFuncAttributeMaxDynamicSharedMemorySize,
                         Bn * (Tn + 1) * 4);

    k_prep_a<<<(768 * 48 * 32) / 256, 256>>>(sent, emb);
    k_prep_b<<<(288 * 48 * 32) / 256, 256>>>(w_ih);
    k_prep_w<<<GRP_NB, 256>>>(w_hh);
    k_xp_mma<<<dim3(D3 / 128, (Bn * Tn) / 128), 256>>>(b_ih);
    k_gru<<<NB, 256, SMEM_GRU>>>(b_hh);
    k_probs<<<(Bn * Tn) / 8, 256>>>(w_act, b_act, out + (size_t)Bn * Tn * Dn);
    k_halt<<<1, 384, Bn * (Tn + 1) * 4>>>();
    k_out<<<Bn * Tn, 128>>>(out);
}

// round 13
// speedup vs baseline: 1.0079x; 1.0079x over previous
#include <cuda_runtime.h>
#include <cuda_bf16.h>
#include <math.h>

#define Bn 32
#define Tn 384
#define Dn 768
#define D3 2304
#define NB 96
#define GRP_NB 48
#define THRESH 0.95f

__device__ float g_xp[(size_t)Bn * Tn * D3];
__device__ float g_states[(size_t)Bn * Tn * Dn];
__device__ float g_probs[Bn * Tn];
__device__ float g_weights[Bn * Tn];
__device__ int   g_segend[Bn * Tn];
__device__ int   g_nsegs[Bn];
__device__ volatile int g_flag[NB];
__device__ int   g_done;

// h exchange in m16n8k8 A-frag layout, per group+parity: [grp][par][96 ktile][128]
__device__ float g_hfrag[2][2][96 * 128];
// w_hh fp32 fragment-permuted per column-slice: [cidx 48][ks 8][q 12][nt 6][lane 32][2]
#define WFG (8 * 12 * 6 * 32 * 2)
__device__ float g_wfrag[(size_t)GRP_NB * WFG];

// xp GEMM operands pre-permuted into bf16 mma-fragment order:
// A: [m-tile 768][kt 48][plane hi/lo][lane 32][4 words]
// B: [n-tile 288][kt 48][lane 32][4 words: b0h, b1h, b0l, b1l]
__device__ unsigned g_fA[(size_t)768 * 48 * 2 * 32 * 4];
__device__ unsigned g_fB[(size_t)288 * 48 * 32 * 4];

__device__ __forceinline__ void bsplit(float2 p, unsigned& hi, unsigned& lo) {
    __nv_bfloat16 hx = __float2bfloat16(p.x);
    __nv_bfloat16 hy = __float2bfloat16(p.y);
    __nv_bfloat162 h; h.x = hx; h.y = hy;
    float lx = p.x - __bfloat162float(hx);
    float ly = p.y - __bfloat162float(hy);
    __nv_bfloat162 l = __floats2bfloat162_rn(lx, ly);
    hi = *(unsigned*)&h; lo = *(unsigned*)&l;
}

// ============ prep A: gather emb[sent] -> frag-ordered planes (hi plane, lo plane)
__global__ __launch_bounds__(256) void k_prep_a(const int* __restrict__ sent,
                                                const float* __restrict__ emb) {
    int idx = blockIdx.x * 256 + threadIdx.x;   // over 768*48*32
    int lane = idx & 31;
    int kt = (idx >> 5) % 48;
    int tm = idx / (48 * 32);
    int k0 = kt * 16 + (lane & 3) * 2;
    int m0 = tm * 16 + (lane >> 2);
    const float* x0 = emb + (size_t)sent[m0] * Dn;
    const float* x1 = emb + (size_t)sent[m0 + 8] * Dn;
    float2 p00 = *(const float2*)(x0 + k0);
    float2 p10 = *(const float2*)(x1 + k0);
    float2 p01 = *(const float2*)(x0 + k0 + 8);
    float2 p11 = *(const float2*)(x1 + k0 + 8);
    unsigned* dh = g_fA + (size_t)(tm * 48 + kt) * 256 + lane * 4;  // hi plane
    unsigned* dl = dh + 128;                                        // lo plane
    unsigned h, l;
    bsplit(p00, h, l); dh[0] = h; dl[0] = l;
    bsplit(p10, h, l); dh[1] = h; dl[1] = l;
    bsplit(p01, h, l); dh[2] = h; dl[2] = l;
    bsplit(p11, h, l); dh[3] = h; dl[3] = l;
}

// ============ prep B: w_ih -> frag-ordered hi/lo planes
__global__ __launch_bounds__(256) void k_prep_b(const float* __restrict__ w_ih) {
    int idx = blockIdx.x * 256 + threadIdx.x;   // over 288*48*32
    int lane = idx & 31;
    int kt = (idx >> 5) % 48;
    int tn = idx / (48 * 32);
    int n = tn * 8 + (lane >> 2);
    int k0 = kt * 16 + (lane & 3) * 2;
    const float* wr = w_ih + (size_t)n * Dn;
    float2 p0 = *(const float2*)(wr + k0);
    float2 p1 = *(const float2*)(wr + k0 + 8);
    unsigned* dst = g_fB + (size_t)idx * 4;
    unsigned h, l;
    bsplit(p0, h, l); dst[0] = h; dst[2] = l;
    bsplit(p1, h, l); dst[1] = h; dst[3] = l;
}

// ============ prep: w_hh -> fp32 B-fragment layout (per 16-col slice)
__global__ __launch_bounds__(256) void k_prep_w(const float* __restrict__ w_hh) {
    int cidx = blockIdx.x;
    int c0 = cidx * 16;
    for (int it = 0; it < WFG / 256; it++) {
        int idx = it * 256 + threadIdx.x;
        int word = idx & 1;
        int lane = (idx >> 1) & 31;
        int f = idx >> 6;
        int nt = f % 6;
        int q = (f / 6) % 12;
        int ks = f / 72;
        int n = nt * 8 + (lane >> 2);
        int j = n >> 4, col = n & 15;
        int gr = j * Dn + c0 + col;
        int k = ks * 96 + q * 8 + (lane & 3) + 4 * word;
        g_wfrag[(size_t)cidx * WFG + idx] = w_hh[(size_t)gr * Dn + k];
    }
}

// ============ Kernel 1: xp mma — frag-ordered GMEM, coalesced SMEM staging,
// conflict-free LDS.128 consumer.
__device__ __forceinline__ void mma_bf16(float* c, const unsigned* a, const unsigned* b) {
    asm volatile(
        "mma.sync.aligned.m16n8k16.row.col.f32.bf16.bf16.f32 "
        "{%0,%1,%2,%3}, {%4,%5,%6,%7}, {%8,%9}, {%0,%1,%2,%3};"
        : "+f"(c[0]), "+f"(c[1]), "+f"(c[2]), "+f"(c[3])
        : "r"(a[0]), "r"(a[1]), "r"(a[2]), "r"(a[3]), "r"(b[0]), "r"(b[1]));
}

__global__ __launch_bounds__(256, 1) void k_xp_mma(const float* __restrict__ b_ih) {
    // A: 8 tiles x (hi/lo x 32 lanes) = 512 uint4; B: 16 tiles x 32 = 512 uint4
    __shared__ uint4 sA[2][512];
    __shared__ uint4 sB[2][512];

    const int tid = threadIdx.x;
    const int bm = blockIdx.y * 128;
    const int bn = blockIdx.x * 128;
    const int warp = tid >> 5;
    const int lane = tid & 31;
    const int wm = warp >> 2;       // 0..1
    const int wn = warp & 3;        // 0..3
    const int gid = lane >> 2;
    const int tig = lane & 3;

    const uint4* aptr = (const uint4*)g_fA;   // per tile-kt: 64 uint4
    const uint4* bptr = (const uint4*)g_fB;   // per tile-kt: 32 uint4

    // copy identity: 4 elements per thread, e = tid + k*256 over [0,1024)
    // e<512 -> A (tile = e>>6, off = e&63); else B (tile = (e-512)>>5, off&31)
    float acc[4][4][4];
#pragma unroll
    for (int i = 0; i < 4; i++)
#pragma unroll
        for (int j = 0; j < 4; j++)
#pragma unroll
            for (int r = 0; r < 4; r++) acc[i][j][r] = 0.f;

    // stage kt=0 directly
#pragma unroll
    for (int k = 0; k < 4; k++) {
        int e = tid + k * 256;
        if (e < 512) {
            int i = e >> 6, off = e & 63;
            sA[0][e] = aptr[((size_t)(blockIdx.y * 8 + i) * 48 + 0) * 64 + off];
        } else {
            int e2 = e - 512, j = e2 >> 5, off = e2 & 31;
            sB[0][e2] = bptr[((size_t)(blockIdx.x * 16 + j) * 48 + 0) * 32 + off];
        }
    }

    for (int kt = 0; kt < 48; kt++) {
        const int cb = kt & 1;
        uint4 pr[4];
        if (kt + 1 < 48) {
#pragma unroll
            for (int k = 0; k < 4; k++) {
                int e = tid + k * 256;
                if (e < 512) {
                    int i = e >> 6, off = e & 63;
                    pr[k] = aptr[((size_t)(blockIdx.y * 8 + i) * 48 + kt + 1) * 64 + off];
                } else {
                    int e2 = e - 512, j = e2 >> 5, off = e2 & 31;
                    pr[k] = bptr[((size_t)(blockIdx.x * 16 + j) * 48 + kt + 1) * 32 + off];
                }
            }
        }
        __syncthreads();

        unsigned Ah[4][4], Al[4][4], Bf[4][4];
#pragma unroll
        for (int i = 0; i < 4; i++) {
            *(uint4*)Ah[i] = sA[cb][(wm * 4 + i) * 64 + lane];        // hi plane
            *(uint4*)Al[i] = sA[cb][(wm * 4 + i) * 64 + 32 + lane];   // lo plane
            *(uint4*)Bf[i] = sB[cb][(wn * 4 + i) * 32 + lane];
        }
#pragma unroll
        for (int i = 0; i < 4; i++)
#pragma unroll
            for (int j = 0; j < 4; j++) {
                mma_bf16(acc[i][j], Ah[i], &Bf[j][0]);
                mma_bf16(acc[i][j], Al[i], &Bf[j][0]);
                mma_bf16(acc[i][j], Ah[i], &Bf[j][2]);
            }

        if (kt + 1 < 48) {
            const int nb = cb ^ 1;
#pragma unroll
            for (int k = 0; k < 4; k++) {
                int e = tid + k * 256;
                if (e < 512) sA[nb][e] = pr[k];
                else sB[nb][e - 512] = pr[k];
            }
        }
    }

#pragma unroll
    for (int j = 0; j < 4; j++) {
        int ncol = bn + (wn * 4 + j) * 8 + 2 * tig;
        float2 bias = *(const float2*)&b_ih[ncol];
#pragma unroll
        for (int i = 0; i < 4; i++) {
            int m0 = bm + (wm * 4 + i) * 16 + gid;
            float2 v0 = {acc[i][j][0] + bias.x, acc[i][j][1] + bias.y};
            float2 v1 = {acc[i][j][2] + bias.x, acc[i][j][3] + bias.y};
            *(float2*)(g_xp + (size_t)m0 * D3 + ncol) = v0;
            *(float2*)(g_xp + (size_t)(m0 + 8) * D3 + ncol) = v1;
        }
    }
}

// ============ Kernel 2: GRU, 2 groups of 48 blocks; h-frags batch-loaded (MLP 12)
#define SM_PARTG (8 * 48 * 17)
#define SMEM_GRU ((WFG + SM_PARTG) * 4)

__device__ __forceinline__ void mma_tf32(float* c, const float4 a, float b0, float b1) {
    asm volatile(
        "mma.sync.aligned.m16n8k8.row.col.f32.tf32.tf32.f32 "
        "{%0,%1,%2,%3}, {%4,%5,%6,%7}, {%8,%9}, {%0,%1,%2,%3};"
        : "+f"(c[0]), "+f"(c[1]), "+f"(c[2]), "+f"(c[3])
        : "r"(__float_as_uint(a.x)), "r"(__float_as_uint(a.y)),
          "r"(__float_as_uint(a.z)), "r"(__float_as_uint(a.w)),
          "r"(__float_as_uint(b0)), "r"(__float_as_uint(b1)));
}
__device__ __forceinline__ float tf_hi1(float a) {
    return __uint_as_float(__float_as_uint(a) & 0xffffe000u);
}
__device__ __forceinline__ float4 tf_hi(float4 a) {
    return make_float4(tf_hi1(a.x), tf_hi1(a.y), tf_hi1(a.z), tf_hi1(a.w));
}
__device__ __forceinline__ float4 f4sub(float4 a, float4 b) {
    return make_float4(a.x - b.x, a.y - b.y, a.z - b.z, a.w - b.w);
}

__global__ __launch_bounds__(256, 1) void k_gru(const float* __restrict__ b_hh) {
    extern __shared__ float sm[];
    float* wf = sm;
    float* part = sm + WFG;

    const int tid = threadIdx.x;
    const int bid = blockIdx.x;
    const int grp = bid / GRP_NB;
    const int cidx = bid - grp * GRP_NB;
    const int c0 = cidx * 16;
    const int b0 = grp * 16;

    {
        const float4* src = (const float4*)(g_wfrag + (size_t)cidx * WFG);
        float4* dst = (float4*)wf;
        for (int i = tid; i < WFG / 4; i += 256) dst[i] = src[i];
    }

    const int lane = tid & 31;
    const int ks = tid >> 5;

    const int gc = tid >> 4;
    const int gb = tid & 15;
    const float br = b_hh[c0 + gc];
    const float bz = b_hh[Dn + c0 + gc];
    const float bnn = b_hh[2 * Dn + c0 + gc];
    const int c = c0 + gc;
    const int ktile = c >> 3, kin = c & 7;
    const int gw = ktile * 128 + ((gb & 7) * 4 + (kin & 3)) * 4 +
                   ((gb >> 3) + 2 * (kin >> 2));
    float hold = 0.f;

    g_hfrag[grp][0][gw] = 0.f;
    __syncthreads();
    if (tid == 0) { __threadfence(); g_flag[bid] = 1; }
    if (tid < GRP_NB) { while (g_flag[grp * GRP_NB + tid] < 1) {} }
    __threadfence();
    __syncthreads();

    for (int t = 0; t < Tn; t++) {
        const int par = t & 1;

        size_t mrow = (size_t)((b0 + gb) * Tn + t) * D3 + c0 + gc;
        float xr = g_xp[mrow];
        float xz = g_xp[mrow + Dn];
        float xn = g_xp[mrow + 2 * Dn];

        const float* hf = g_hfrag[grp][par];
        const int abase = (ks * 12) * 128 + lane * 4;

        float4 hreg[12];
#pragma unroll
        for (int q = 0; q < 12; q++)
            hreg[q] = __ldcv((const float4*)(hf + abase + q * 128));

        float acc[6][4];
#pragma unroll
        for (int nt = 0; nt < 6; nt++)
#pragma unroll
            for (int r = 0; r < 4; r++) acc[nt][r] = 0.f;

#pragma unroll
        for (int q = 0; q < 12; q++) {
            float4 ahi = tf_hi(hreg[q]);
            float4 alo = f4sub(hreg[q], ahi);
#pragma unroll
            for (int nt = 0; nt < 6; nt++) {
                float2 wv = *(const float2*)&wf[(((ks * 12 + q) * 6) + nt) * 64 + lane * 2];
                float bh0 = tf_hi1(wv.x), bh1 = tf_hi1(wv.y);
                float bl0 = wv.x - bh0, bl1 = wv.y - bh1;
                mma_tf32(acc[nt], ahi, bh0, bh1);
                mma_tf32(acc[nt], alo, bh0, bh1);
                mma_tf32(acc[nt], ahi, bl0, bl1);
            }
        }

#pragma unroll
        for (int nt = 0; nt < 6; nt++)
#pragma unroll
            for (int r = 0; r < 4; r++)
                part[ks * (48 * 17) + (nt * 8 + (lane & 3) * 2 + (r & 1)) * 17 +
                     (lane >> 2) + 8 * (r >> 1)] = acc[nt][r];
        __syncthreads();

        {
            float hr = br, hz = bz, hn = bnn;
#pragma unroll
            for (int s2 = 0; s2 < 8; s2++) {
                const float* pp = part + s2 * (48 * 17);
                hr += pp[gc * 17 + gb];
                hz += pp[(16 + gc) * 17 + gb];
                hn += pp[(32 + gc) * 17 + gb];
            }
            float r = 1.f / (1.f + expf(-(xr + hr)));
            float z = 1.f / (1.f + expf(-(xz + hz)));
            float n = tanhf(xn + r * hn);
            float hnew = (1.f - z) * n + z * hold;
            hold = hnew;
            g_hfrag[grp][par ^ 1][gw] = hnew;
            g_states[(size_t)((b0 + gb) * Tn + t) * Dn + c0 + gc] = hnew;
        }

        __syncthreads();
        if (tid == 0) { __threadfence(); g_flag[bid] = t + 2; }
        if (tid < GRP_NB) { while (g_flag[grp * GRP_NB + tid] < t + 2) {} }
        __threadfence();
        __syncthreads();
    }

    if (tid == 0) {
        int old = atomicAdd(&g_done, 1);
        if (old == NB - 1) {
            for (int i = 0; i < NB; i++) g_flag[i] = 0;
            __threadfence();
            g_done = 0;
        }
    }
}

// ============ Kernel 3: probs
__global__ __launch_bounds__(256) void k_probs(const float* __restrict__ w_act,
                                               const float* __restrict__ b_act,
                                               float* __restrict__ out_probs) {
    int warp = threadIdx.x >> 5, lane = threadIdx.x & 31;
    int m = blockIdx.x * 8 + warp;
    const float4* row = (const float4*)(g_states + (size_t)m * Dn);
    const float4* wv = (const float4*)w_act;
    float acc = 0.f;
    for (int i = lane; i < 192; i += 32) {
        float4 v = row[i], w = wv[i];
        acc += v.x * w.x + v.y * w.y + v.z * w.z + v.w * w.w;
    }
#pragma unroll
    for (int off = 16; off; off >>= 1) acc += __shfl_down_sync(0xffffffffu, acc, off);
    if (lane == 0) {
        float p = 1.f / (1.f + expf(-(acc + b_act[0])));
        g_probs[m] = p;
        out_probs[m] = p;
    }
}

// ============ Kernel 4: ACT halting scan
__global__ void k_halt() {
    extern __shared__ float ps[];
    int tid = threadIdx.x;
    for (int i = tid; i < Bn * Tn; i += 384) {
        int b = i / Tn, t = i - b * Tn;
        ps[b * (Tn + 1) + t] = g_probs[i];
    }
    __syncthreads();
    if (tid < Bn) {
        int b = tid;
        const float* pb = ps + b * (Tn + 1);
        float acc = 0.f;
        int ns = 0;
        for (int t = 0; t < Tn; t++) {
            float p = pb[t];
            float a = acc + p;
            if (a > THRESH) {
                g_weights[b * Tn + t] = p - (a - 1.f);
                g_segend[b * Tn + ns] = t;
                ns++;
                acc = 0.f;
            } else {
                g_weights[b * Tn + t] = p;
                acc = a;
            }
        }
        g_nsegs[b] = ns;
    }
}

// ============ Kernel 5: segment sums -> output embs
__global__ __launch_bounds__(128) void k_out(float* __restrict__ out) {
    int bs = blockIdx.x;
    int b = bs / Tn, s = bs - b * Tn;
    float* o = out + (size_t)bs * Dn;
    int tid = threadIdx.x;
    if (s >= g_nsegs[b]) {
        for (int d = tid; d < Dn; d += 128) o[d] = 0.f;
        return;
    }
    int t1 = g_segend[b * Tn + s];
    int t0 = (s == 0) ? 0 : g_segend[b * Tn + s - 1] + 1;
    for (int d = tid; d < Dn; d += 128) {
        float sum = 0.f;
        for (int t = t0; t <= t1; t++)
            sum += g_states[(size_t)(b * Tn + t) * Dn + d] * g_weights[b * Tn + t];
        o[d] = sum;
    }
}

extern "C" void kernel_launch(void* const* d_in, const int* in_sizes, int n_in,
                              void* d_out, int out_size) {
    const int* sent    = (const int*)d_in[0];
    const float* emb   = (const float*)d_in[1];
    const float* w_ih  = (const float*)d_in[2];
    const float* w_hh  = (const float*)d_in[3];
    const float* b_ih  = (const float*)d_in[4];
    const float* b_hh  = (const float*)d_in[5];
    const float* w_act = (const float*)d_in[6];
    const float* b_act = (const float*)d_in[7];
    float* out = (float*)d_out;

    cudaFuncSetAttribute(k_gru, cudaFuncAttributeMaxDynamicSharedMemorySize, SMEM_GRU);
    cudaFuncSetAttribute(k_halt, cudaFuncAttributeMaxDynamicSharedMemorySize,
                         Bn * (Tn + 1) * 4);

    k_prep_a<<<(768 * 48 * 32) / 256, 256>>>(sent, emb);
    k_prep_b<<<(288 * 48 * 32) / 256, 256>>>(w_ih);
    k_prep_w<<<GRP_NB, 256>>>(w_hh);
    k_xp_mma<<<dim3(D3 / 128, (Bn * Tn) / 128), 256>>>(b_ih);
    k_gru<<<NB, 256, SMEM_GRU>>>(b_hh);
    k_probs<<<(Bn * Tn) / 8, 256>>>(w_act, b_act, out + (size_t)Bn * Tn * Dn);
    k_halt<<<1, 384, Bn * (Tn + 1) * 4>>>();
    k_out<<<Bn * Tn, 128>>>(out);
}